// round 12
// baseline (speedup 1.0000x reference)
#include <cuda_runtime.h>
#include <cuda_fp16.h>
#include <cstdint>

#define MTOT 8192      // B*S
#define DIN  4096
#define DOUT 4096
#define RANK 16
#define NR   128       // N_adapters * RANK
#define LORA_SCALE 2.0f

// ---- scratch (__device__ globals per allocation rules) ----
__device__ __half g_xh[MTOT * DIN];   // fp16 x
__device__ __half g_Wh[DOUT * DIN];   // fp16 W
__device__ __half g_Ah[NR * DIN];     // fp16 lora_A
__device__ __half g_hh[MTOT * NR];    // fp16 low-rank acts
__device__ __half g_Bch[DOUT * NR];   // fp16 coef-fused lora_B

__device__ __forceinline__ uint32_t s2u(const void* p) {
    return (uint32_t)__cvta_generic_to_shared(p);
}
__device__ __forceinline__ void cp16(uint32_t dst, const void* src) {
    asm volatile("cp.async.cg.shared.global [%0], [%1], 16;\n"
                 :: "r"(dst), "l"(src));
}
__device__ __forceinline__ void cp_commit() {
    asm volatile("cp.async.commit_group;" ::: "memory");
}
template<int N>
__device__ __forceinline__ void cp_wait() {
    asm volatile("cp.async.wait_group %0;" :: "n"(N) : "memory");
}
__device__ __forceinline__ void ldsm_x4(uint32_t& r0, uint32_t& r1,
                                        uint32_t& r2, uint32_t& r3, uint32_t a) {
    asm volatile("ldmatrix.sync.aligned.m8n8.x4.shared.b16 {%0,%1,%2,%3}, [%4];"
                 : "=r"(r0), "=r"(r1), "=r"(r2), "=r"(r3) : "r"(a));
}

// ---- combined fp32 -> fp16 conversion for x, W, lora_A (one launch) ----
#define N4X (MTOT * DIN / 4)
#define N4W (DOUT * DIN / 4)
#define N4A (NR * DIN / 4)

__global__ void f2h_all_kernel(const float4* __restrict__ x,   uint2* __restrict__ xh,
                               const float4* __restrict__ W,   uint2* __restrict__ Wh,
                               const float4* __restrict__ A,   uint2* __restrict__ Ah)
{
    const int total = N4X + N4W + N4A;
    for (int i = blockIdx.x * blockDim.x + threadIdx.x; i < total;
         i += gridDim.x * blockDim.x) {
        const float4* in; uint2* out; int j = i;
        if (j < N4X)            { in = x; out = xh; }
        else if ((j -= N4X) < N4W) { in = W; out = Wh; }
        else                    { j -= N4W; in = A; out = Ah; }
        float4 v = in[j];
        __half2 h0 = __floats2half2_rn(v.x, v.y);
        __half2 h1 = __floats2half2_rn(v.z, v.w);
        uint2 o;
        o.x = *reinterpret_cast<unsigned*>(&h0);
        o.y = *reinterpret_cast<unsigned*>(&h1);
        out[j] = o;
    }
}

// Bc[o][n*16+r] = fp16(SCALE * lw[n] * lora_B[n][o][r])
__global__ void build_bc_kernel(const float* __restrict__ lora_B,
                                const float* __restrict__ lw) {
    int idx = blockIdx.x * blockDim.x + threadIdx.x;
    if (idx >= DOUT * NR) return;
    int o  = idx / NR;
    int nr = idx - o * NR;
    int n  = nr >> 4;
    int r  = nr & 15;
    g_Bch[idx] = __float2half_rn(
        (LORA_SCALE * lw[n]) * lora_B[((size_t)n * DOUT + o) * RANK + r]);
}

// ============================================================================
// GEMM1 (round-8 proven): fp16 mma, 64x128, BK=32, padded smem, 256 thr.
// h = x_h @ A_h^T
// ============================================================================
__global__ __launch_bounds__(256, 2)
void gemm1_f16(const __half* __restrict__ A1, int lda1,
               const __half* __restrict__ B1, int ldb1, int K1,
               __half* __restrict__ C, int ldc)
{
    constexpr int BM = 64, BN = 128;
    constexpr int S = 3;
    constexpr int MI = 2;
    constexpr int LDS_ = 40;
    constexpr int AST = BM * LDS_;
    constexpr int BST = BN * LDS_;
    constexpr int STG = AST + BST;

    extern __shared__ __half smem[];

    const int tid  = threadIdx.x;
    const int wid  = tid >> 5;
    const int lane = tid & 31;
    const int gid  = lane >> 2;
    const int tig  = lane & 3;
    const int warpRow = (wid >> 2) * 32;
    const int warpCol = (wid & 3) * 32;

    const size_t mBase = (size_t)blockIdx.y * BM;
    const int nIter = K1 / 32;
    const uint32_t smemB = s2u(smem);

    auto issue = [&](int k) {
        int slot = k % S;
        uint32_t aS = smemB + slot * STG * 2;
        uint32_t bS = aS + AST * 2;
        int kk = k * 32;
        {
            int idx = tid, row = idx >> 2, c8 = (idx & 3) << 3;
            cp16(aS + (row * LDS_ + c8) * 2,
                 A1 + (mBase + row) * (size_t)lda1 + kk + c8);
        }
        #pragma unroll
        for (int i = 0; i < 2; i++) {
            int idx = tid + i * 256, row = idx >> 2, c8 = (idx & 3) << 3;
            cp16(bS + (row * LDS_ + c8) * 2,
                 B1 + row * (size_t)ldb1 + kk + c8);
        }
    };

    float acc[MI][4][4];
    #pragma unroll
    for (int i = 0; i < MI; i++)
        #pragma unroll
        for (int j = 0; j < 4; j++)
            #pragma unroll
            for (int k = 0; k < 4; k++) acc[i][j][k] = 0.f;

    #pragma unroll
    for (int k = 0; k < S - 1; k++) { if (k < nIter) issue(k); cp_commit(); }

    for (int k = 0; k < nIter; k++) {
        cp_wait<S - 2>();
        __syncthreads();
        if (k + S - 1 < nIter) issue(k + S - 1);
        cp_commit();

        const __half* As = smem + (k % S) * STG;
        const __half* Bs = As + AST;

        #pragma unroll
        for (int ks = 0; ks < 2; ks++) {
            const int k0 = ks * 16;
            unsigned af[MI][4], bf[4][2];
            #pragma unroll
            for (int mi = 0; mi < MI; mi++) {
                const __half* a = As + (warpRow + mi * 16 + gid) * LDS_ + k0 + 2 * tig;
                af[mi][0] = *reinterpret_cast<const unsigned*>(a);
                af[mi][1] = *reinterpret_cast<const unsigned*>(a + 8 * LDS_);
                af[mi][2] = *reinterpret_cast<const unsigned*>(a + 8);
                af[mi][3] = *reinterpret_cast<const unsigned*>(a + 8 * LDS_ + 8);
            }
            #pragma unroll
            for (int ni = 0; ni < 4; ni++) {
                const __half* b = Bs + (warpCol + ni * 8 + gid) * LDS_ + k0 + 2 * tig;
                bf[ni][0] = *reinterpret_cast<const unsigned*>(b);
                bf[ni][1] = *reinterpret_cast<const unsigned*>(b + 8);
            }
            #pragma unroll
            for (int mi = 0; mi < MI; mi++)
                #pragma unroll
                for (int ni = 0; ni < 4; ni++) {
                    asm volatile(
                        "mma.sync.aligned.m16n8k16.row.col.f32.f16.f16.f32 "
                        "{%0,%1,%2,%3}, {%4,%5,%6,%7}, {%8,%9}, {%0,%1,%2,%3};"
                        : "+f"(acc[mi][ni][0]), "+f"(acc[mi][ni][1]),
                          "+f"(acc[mi][ni][2]), "+f"(acc[mi][ni][3])
                        : "r"(af[mi][0]), "r"(af[mi][1]),
                          "r"(af[mi][2]), "r"(af[mi][3]),
                          "r"(bf[ni][0]), "r"(bf[ni][1]));
                }
        }
    }

    #pragma unroll
    for (int mi = 0; mi < MI; mi++) {
        size_t row = mBase + warpRow + mi * 16 + gid;
        #pragma unroll
        for (int ni = 0; ni < 4; ni++) {
            size_t col = warpCol + ni * 8 + tig * 2;
            __half2 v0 = __floats2half2_rn(acc[mi][ni][0], acc[mi][ni][1]);
            __half2 v1 = __floats2half2_rn(acc[mi][ni][2], acc[mi][ni][3]);
            *reinterpret_cast<__half2*>(C + row * (size_t)ldc + col)       = v0;
            *reinterpret_cast<__half2*>(C + (row + 8) * (size_t)ldc + col) = v1;
        }
    }
}

// ============================================================================
// Main GEMM: 128x128 tile, BK=64, 128 threads (warps 2x2, warp tile 64x64),
// SW128, ldmatrix, 3-stage cp.async pipeline + cross-iteration prefetch.
// 2 CTAs/SM (96KB smem, <=256 regs) so barrier seams overlap across CTAs.
// C = A1[M,K1]@B1[N,K1]^T + A2[M,K2]@B2[N,K2]^T (ld=NR) + bias
// ============================================================================
__global__ __launch_bounds__(128, 2)
void gemm_f16_big(const __half* __restrict__ A1, int lda1,
                  const __half* __restrict__ B1, int ldb1, int K1,
                  const __half* __restrict__ A2, const __half* __restrict__ B2,
                  int K2,
                  const float* __restrict__ bias,
                  float* __restrict__ C, int ldc)
{
    constexpr int BM = 128, BN = 128;
    constexpr int S  = 3;
    constexpr int AST = BM * 128;             // 16384 B
    constexpr int STG = (BM + BN) * 128;      // 32768 B per stage
    constexpr int MI = 4, NI = 8;             // warp tile 64x64

    extern __shared__ __half smem[];

    const int tid  = threadIdx.x;
    const int wid  = tid >> 5;
    const int lane = tid & 31;
    const int gid  = lane >> 2;
    const int tig  = lane & 3;
    const int warpRow = (wid & 1) * 64;       // 2 warps in M
    const int warpCol = (wid >> 1) * 64;      // 2 warps in N

    const size_t mBase = (size_t)blockIdx.y * BM;
    const size_t nBase = (size_t)blockIdx.x * BN;

    const int n1    = K1 / 64;
    const int nIter = n1 + K2 / 64;
    const uint32_t tiles = s2u(smem);

    // ---- per-lane ldmatrix base offsets (SW128, pre-swizzled, ks=0) ----
    const int quad = lane >> 3, l8 = lane & 7;
    const int arow = warpRow + ((quad & 1) << 3) + l8;
    const uint32_t aoff0 =
        (uint32_t)(arow * 128 + ((((quad >> 1) << 4)) ^ ((arow & 7) << 4)));
    const int brow = warpCol + ((quad >> 1) << 3) + l8;
    const uint32_t boff0 =
        (uint32_t)(AST + brow * 128 + ((((quad & 1) << 4)) ^ ((brow & 7) << 4)));

    // part 0: A tile (8 cp16/thread); part 1: B rows 0-63; part 2: B rows 64-127
    auto issue = [&](int k, int part) {
        int slot = k % S;
        uint32_t base = tiles + slot * STG;
        const __half *Ap, *Bp; int ldA, ldB, kk;
        if (k < n1) { Ap = A1; Bp = B1; ldA = lda1; ldB = ldb1; kk = k * 64; }
        else        { Ap = A2; Bp = B2; ldA = NR;   ldB = NR;   kk = (k - n1) * 64; }
        if (part == 0) {
            #pragma unroll
            for (int i = 0; i < 8; i++) {
                int idx = tid + i * 128, row = idx >> 3, c16 = idx & 7;
                cp16(base + row * 128 + ((c16 * 16) ^ ((row & 7) << 4)),
                     Ap + (mBase + row) * (size_t)ldA + kk + c16 * 8);
            }
        } else {
            #pragma unroll
            for (int i = 0; i < 4; i++) {
                int idx = tid + (part - 1) * 512 + i * 128;
                int row = idx >> 3, c16 = idx & 7;
                cp16(base + AST + row * 128 + ((c16 * 16) ^ ((row & 7) << 4)),
                     Bp + (nBase + row) * (size_t)ldB + kk + c16 * 8);
            }
        }
    };

    float acc[MI][NI][4];
    #pragma unroll
    for (int i = 0; i < MI; i++)
        #pragma unroll
        for (int j = 0; j < NI; j++)
            #pragma unroll
            for (int k = 0; k < 4; k++) acc[i][j][k] = 0.f;

    unsigned afX[MI][4], bgX[NI / 2][4];      // pingpong fragment buffers
    unsigned afY[MI][4], bgY[NI / 2][4];

    auto loadfrags = [&](uint32_t sbase, int ks,
                         unsigned af[MI][4], unsigned bg[NI / 2][4]) {
        const uint32_t kx = (uint32_t)(ks << 5);
        #pragma unroll
        for (int mi = 0; mi < MI; mi++)
            ldsm_x4(af[mi][0], af[mi][1], af[mi][2], af[mi][3],
                    (sbase + aoff0 + mi * 2048) ^ kx);
        #pragma unroll
        for (int g = 0; g < NI / 2; g++)
            ldsm_x4(bg[g][0], bg[g][1], bg[g][2], bg[g][3],
                    (sbase + boff0 + g * 2048) ^ kx);
    };

    auto domma = [&](unsigned af[MI][4], unsigned bg[NI / 2][4]) {
        #pragma unroll
        for (int mi = 0; mi < MI; mi++)
            #pragma unroll
            for (int ni = 0; ni < NI; ni++) {
                unsigned b0 = bg[ni >> 1][(ni & 1) * 2];
                unsigned b1 = bg[ni >> 1][(ni & 1) * 2 + 1];
                asm volatile(
                    "mma.sync.aligned.m16n8k16.row.col.f32.f16.f16.f32 "
                    "{%0,%1,%2,%3}, {%4,%5,%6,%7}, {%8,%9}, {%0,%1,%2,%3};"
                    : "+f"(acc[mi][ni][0]), "+f"(acc[mi][ni][1]),
                      "+f"(acc[mi][ni][2]), "+f"(acc[mi][ni][3])
                    : "r"(af[mi][0]), "r"(af[mi][1]),
                      "r"(af[mi][2]), "r"(af[mi][3]),
                      "r"(b0), "r"(b1));
            }
    };

    // prologue
    #pragma unroll
    for (int k = 0; k < S - 1; k++) {
        if (k < nIter) { issue(k, 0); issue(k, 1); issue(k, 2); }
        cp_commit();
    }
    cp_wait<S - 2>();
    __syncthreads();
    loadfrags(tiles, 0, afX, bgX);

    for (int k = 0; k < nIter; k++) {
        const uint32_t sbase = tiles + (k % S) * STG;
        const uint32_t snext = tiles + ((k + 1) % S) * STG;
        const bool more = (k + S - 1 < nIter);

        loadfrags(sbase, 1, afY, bgY);
        if (more) issue(k + S - 1, 0);
        domma(afX, bgX);                     // ks0

        loadfrags(sbase, 2, afX, bgX);
        if (more) issue(k + S - 1, 1);
        domma(afY, bgY);                     // ks1

        loadfrags(sbase, 3, afY, bgY);
        if (more) issue(k + S - 1, 2);
        domma(afX, bgX);                     // ks2

        cp_commit();
        cp_wait<S - 2>();                    // stage k+1 resident
        __syncthreads();                     // all stage-k reads done
        loadfrags(snext, 0, afX, bgX);       // prefetch next ks0
        domma(afY, bgY);                     // ks3
    }

    // ---- epilogue: +bias, float2 stores ----
    #pragma unroll
    for (int mi = 0; mi < MI; mi++) {
        size_t row = mBase + warpRow + mi * 16 + gid;
        #pragma unroll
        for (int ni = 0; ni < NI; ni++) {
            size_t col = nBase + warpCol + ni * 8 + tig * 2;
            float b0 = __ldg(bias + col);
            float b1 = __ldg(bias + col + 1);
            float2 v0, v1;
            v0.x = acc[mi][ni][0] + b0; v0.y = acc[mi][ni][1] + b1;
            v1.x = acc[mi][ni][2] + b0; v1.y = acc[mi][ni][3] + b1;
            *reinterpret_cast<float2*>(C + row * (size_t)ldc + col)       = v0;
            *reinterpret_cast<float2*>(C + (row + 8) * (size_t)ldc + col) = v1;
        }
    }
}

extern "C" void kernel_launch(void* const* d_in, const int* in_sizes, int n_in,
                              void* d_out, int out_size) {
    const float* x      = (const float*)d_in[0];
    const float* lora_A = (const float*)d_in[1];
    const float* lora_B = (const float*)d_in[2];
    const float* W      = (const float*)d_in[3];
    const float* bias   = (const float*)d_in[4];
    const float* lw     = (const float*)d_in[5];
    float* out = (float*)d_out;

    __half *xh, *Wh, *Ah, *hh, *bch;
    cudaGetSymbolAddress((void**)&xh,  g_xh);
    cudaGetSymbolAddress((void**)&Wh,  g_Wh);
    cudaGetSymbolAddress((void**)&Ah,  g_Ah);
    cudaGetSymbolAddress((void**)&hh,  g_hh);
    cudaGetSymbolAddress((void**)&bch, g_Bch);

    // 0) all fp32->fp16 conversions in one launch + Bc build
    f2h_all_kernel<<<2048, 256>>>((const float4*)x, (uint2*)xh,
                                  (const float4*)W, (uint2*)Wh,
                                  (const float4*)lora_A, (uint2*)Ah);
    build_bc_kernel<<<(DOUT * NR + 255) / 256, 256>>>(lora_B, lw);

    constexpr int SMEM1   = 3 * (64 + 128) * 40 * 2;    // 46,080 B
    constexpr int SMEMBIG = 3 * (128 + 128) * 128;      // 98,304 B
    cudaFuncSetAttribute(gemm1_f16,
                         cudaFuncAttributeMaxDynamicSharedMemorySize, SMEM1);
    cudaFuncSetAttribute(gemm_f16_big,
                         cudaFuncAttributeMaxDynamicSharedMemorySize, SMEMBIG);

    // 1) h = x @ A^T : [8192,128] fp16, K=4096
    gemm1_f16<<<dim3(1, MTOT / 64), 256, SMEM1>>>(
        xh, DIN, Ah, DIN, DIN, hh, NR);

    // 2) out = x @ W^T + h @ Bc^T + bias : [8192,4096] fp32
    gemm_f16_big<<<dim3(DOUT / 128, MTOT / 128), 128, SMEMBIG>>>(
        xh, DIN, Wh, DIN, DIN,
        hh, bch, NR,
        bias, out, DOUT);
}

// round 15
// speedup vs baseline: 1.0315x; 1.0315x over previous
#include <cuda_runtime.h>
#include <cuda_fp16.h>
#include <cstdint>

#define MTOT 8192      // B*S
#define DIN  4096
#define DOUT 4096
#define RANK 16
#define NR   128       // N_adapters * RANK
#define LORA_SCALE 2.0f

// ---- scratch (__device__ globals per allocation rules) ----
__device__ __half g_xh[MTOT * DIN];   // fp16 x
__device__ __half g_Wh[DOUT * DIN];   // fp16 W
__device__ __half g_Ah[NR * DIN];     // fp16 lora_A
__device__ __half g_hh[MTOT * NR];    // fp16 low-rank acts
__device__ __half g_Bch[DOUT * NR];   // fp16 coef-fused lora_B

__device__ __forceinline__ uint32_t s2u(const void* p) {
    return (uint32_t)__cvta_generic_to_shared(p);
}
__device__ __forceinline__ void cp16(uint32_t dst, const void* src) {
    asm volatile("cp.async.cg.shared.global [%0], [%1], 16;\n"
                 :: "r"(dst), "l"(src));
}
__device__ __forceinline__ void cp_commit() {
    asm volatile("cp.async.commit_group;" ::: "memory");
}
template<int N>
__device__ __forceinline__ void cp_wait() {
    asm volatile("cp.async.wait_group %0;" :: "n"(N) : "memory");
}
__device__ __forceinline__ void ldsm_x4(uint32_t& r0, uint32_t& r1,
                                        uint32_t& r2, uint32_t& r3, uint32_t a) {
    asm volatile("ldmatrix.sync.aligned.m8n8.x4.shared.b16 {%0,%1,%2,%3}, [%4];"
                 : "=r"(r0), "=r"(r1), "=r"(r2), "=r"(r3) : "r"(a));
}

// ---- fp32 -> fp16 conversion for x and lora_A only (one launch) ----
#define N4X (MTOT * DIN / 4)
#define N4A (NR * DIN / 4)

__global__ void f2h_xa_kernel(const float4* __restrict__ x, uint2* __restrict__ xh,
                              const float4* __restrict__ A, uint2* __restrict__ Ah)
{
    const int total = N4X + N4A;
    for (int i = blockIdx.x * blockDim.x + threadIdx.x; i < total;
         i += gridDim.x * blockDim.x) {
        const float4* in; uint2* out; int j = i;
        if (j < N4X) { in = x; out = xh; }
        else         { j -= N4X; in = A; out = Ah; }
        float4 v = in[j];
        __half2 h0 = __floats2half2_rn(v.x, v.y);
        __half2 h1 = __floats2half2_rn(v.z, v.w);
        uint2 o;
        o.x = *reinterpret_cast<unsigned*>(&h0);
        o.y = *reinterpret_cast<unsigned*>(&h1);
        out[j] = o;
    }
}

// Bc[o][n*16+r] = fp16(SCALE * lw[n] * lora_B[n][o][r])
__global__ void build_bc_kernel(const float* __restrict__ lora_B,
                                const float* __restrict__ lw) {
    int idx = blockIdx.x * blockDim.x + threadIdx.x;
    if (idx >= DOUT * NR) return;
    int o  = idx / NR;
    int nr = idx - o * NR;
    int n  = nr >> 4;
    int r  = nr & 15;
    g_Bch[idx] = __float2half_rn(
        (LORA_SCALE * lw[n]) * lora_B[((size_t)n * DOUT + o) * RANK + r]);
}

// ============================================================================
// GEMM1 (round-8 proven) + co-scheduled W conversion.
// blockIdx.y < 128: h = x_h @ A_h^T  (64x128 tile, BK=32, 256 thr).
// blockIdx.y >= 128: W fp32->fp16 grid-stride (64 blocks).
// ============================================================================
#define G1_MBLK 128
#define G1_WBLK 64
#define N4W (DOUT * DIN / 4)

__global__ __launch_bounds__(256, 2)
void gemm1_f16(const __half* __restrict__ A1, int lda1,
               const __half* __restrict__ B1, int ldb1, int K1,
               __half* __restrict__ C, int ldc,
               const float* __restrict__ W, __half* __restrict__ Wh)
{
    const int tid = threadIdx.x;

    if (blockIdx.y >= G1_MBLK) {                // W conversion blocks
        int base = (blockIdx.y - G1_MBLK) * 256 + tid;
        const float4* in = (const float4*)W;
        uint2* out = (uint2*)Wh;
        for (int i = base; i < N4W; i += G1_WBLK * 256) {
            float4 v = in[i];
            __half2 h0 = __floats2half2_rn(v.x, v.y);
            __half2 h1 = __floats2half2_rn(v.z, v.w);
            uint2 o;
            o.x = *reinterpret_cast<unsigned*>(&h0);
            o.y = *reinterpret_cast<unsigned*>(&h1);
            out[i] = o;
        }
        return;
    }

    constexpr int BM = 64, BN = 128;
    constexpr int S = 3;
    constexpr int MI = 2;
    constexpr int LDS_ = 40;
    constexpr int AST = BM * LDS_;
    constexpr int BST = BN * LDS_;
    constexpr int STG = AST + BST;

    extern __shared__ __half smem[];

    const int wid  = tid >> 5;
    const int lane = tid & 31;
    const int gid  = lane >> 2;
    const int tig  = lane & 3;
    const int warpRow = (wid >> 2) * 32;
    const int warpCol = (wid & 3) * 32;

    const size_t mBase = (size_t)blockIdx.y * BM;
    const int nIter = K1 / 32;
    const uint32_t smemB = s2u(smem);

    auto issue = [&](int k) {
        int slot = k % S;
        uint32_t aS = smemB + slot * STG * 2;
        uint32_t bS = aS + AST * 2;
        int kk = k * 32;
        {
            int idx = tid, row = idx >> 2, c8 = (idx & 3) << 3;
            cp16(aS + (row * LDS_ + c8) * 2,
                 A1 + (mBase + row) * (size_t)lda1 + kk + c8);
        }
        #pragma unroll
        for (int i = 0; i < 2; i++) {
            int idx = tid + i * 256, row = idx >> 2, c8 = (idx & 3) << 3;
            cp16(bS + (row * LDS_ + c8) * 2,
                 B1 + row * (size_t)ldb1 + kk + c8);
        }
    };

    float acc[MI][4][4];
    #pragma unroll
    for (int i = 0; i < MI; i++)
        #pragma unroll
        for (int j = 0; j < 4; j++)
            #pragma unroll
            for (int k = 0; k < 4; k++) acc[i][j][k] = 0.f;

    #pragma unroll
    for (int k = 0; k < S - 1; k++) { if (k < nIter) issue(k); cp_commit(); }

    for (int k = 0; k < nIter; k++) {
        cp_wait<S - 2>();
        __syncthreads();
        if (k + S - 1 < nIter) issue(k + S - 1);
        cp_commit();

        const __half* As = smem + (k % S) * STG;
        const __half* Bs = As + AST;

        #pragma unroll
        for (int ks = 0; ks < 2; ks++) {
            const int k0 = ks * 16;
            unsigned af[MI][4], bf[4][2];
            #pragma unroll
            for (int mi = 0; mi < MI; mi++) {
                const __half* a = As + (warpRow + mi * 16 + gid) * LDS_ + k0 + 2 * tig;
                af[mi][0] = *reinterpret_cast<const unsigned*>(a);
                af[mi][1] = *reinterpret_cast<const unsigned*>(a + 8 * LDS_);
                af[mi][2] = *reinterpret_cast<const unsigned*>(a + 8);
                af[mi][3] = *reinterpret_cast<const unsigned*>(a + 8 * LDS_ + 8);
            }
            #pragma unroll
            for (int ni = 0; ni < 4; ni++) {
                const __half* b = Bs + (warpCol + ni * 8 + gid) * LDS_ + k0 + 2 * tig;
                bf[ni][0] = *reinterpret_cast<const unsigned*>(b);
                bf[ni][1] = *reinterpret_cast<const unsigned*>(b + 8);
            }
            #pragma unroll
            for (int mi = 0; mi < MI; mi++)
                #pragma unroll
                for (int ni = 0; ni < 4; ni++) {
                    asm volatile(
                        "mma.sync.aligned.m16n8k16.row.col.f32.f16.f16.f32 "
                        "{%0,%1,%2,%3}, {%4,%5,%6,%7}, {%8,%9}, {%0,%1,%2,%3};"
                        : "+f"(acc[mi][ni][0]), "+f"(acc[mi][ni][1]),
                          "+f"(acc[mi][ni][2]), "+f"(acc[mi][ni][3])
                        : "r"(af[mi][0]), "r"(af[mi][1]),
                          "r"(af[mi][2]), "r"(af[mi][3]),
                          "r"(bf[ni][0]), "r"(bf[ni][1]));
                }
        }
    }

    #pragma unroll
    for (int mi = 0; mi < MI; mi++) {
        size_t row = mBase + warpRow + mi * 16 + gid;
        #pragma unroll
        for (int ni = 0; ni < 4; ni++) {
            size_t col = warpCol + ni * 8 + tig * 2;
            __half2 v0 = __floats2half2_rn(acc[mi][ni][0], acc[mi][ni][1]);
            __half2 v1 = __floats2half2_rn(acc[mi][ni][2], acc[mi][ni][3]);
            *reinterpret_cast<__half2*>(C + row * (size_t)ldc + col)       = v0;
            *reinterpret_cast<__half2*>(C + (row + 8) * (size_t)ldc + col) = v1;
        }
    }
}

// ============================================================================
// Main GEMM (round-8 base): 128x256 tile, BK=64, 256 threads, warp 64x64,
// SW128, 4-stage cp.async pipeline. NEW: LDSM prefetch of the next k-step is
// interleaved INSIDE the 32-HMMA block (2 LDSM per 8 HMMA) to smooth
// LSU/issue bursts and remove step-boundary eligibility gaps.
// ============================================================================
__global__ __launch_bounds__(256, 1)
void gemm_f16_big(const __half* __restrict__ A1, int lda1,
                  const __half* __restrict__ B1, int ldb1, int K1,
                  const __half* __restrict__ A2, const __half* __restrict__ B2,
                  int K2,
                  const float* __restrict__ bias,
                  float* __restrict__ C, int ldc)
{
    constexpr int BM = 128, BN = 256;
    constexpr int S  = 4;
    constexpr int AST = BM * 128;
    constexpr int STG = (BM + BN) * 128;      // 49152 B per stage
    constexpr int MI = 4, NI = 8;             // warp tile 64x64

    extern __shared__ __half smem[];

    const int tid  = threadIdx.x;
    const int wid  = tid >> 5;
    const int lane = tid & 31;
    const int gid  = lane >> 2;
    const int tig  = lane & 3;
    const int warpRow = (wid & 1) * 64;
    const int warpCol = (wid >> 1) * 64;

    const size_t mBase = (size_t)blockIdx.y * BM;
    const size_t nBase = (size_t)blockIdx.x * BN;

    const int n1    = K1 / 64;
    const int nIter = n1 + K2 / 64;
    const uint32_t tiles = s2u(smem);

    // ---- per-lane ldmatrix base offsets (SW128, pre-swizzled, ks=0) ----
    const int quad = lane >> 3, l8 = lane & 7;
    const int arow = warpRow + ((quad & 1) << 3) + l8;
    const uint32_t aoff0 =
        (uint32_t)(arow * 128 + ((((quad >> 1) << 4)) ^ ((arow & 7) << 4)));
    const int brow = warpCol + ((quad >> 1) << 3) + l8;
    const uint32_t boff0 =
        (uint32_t)(AST + brow * 128 + ((((quad & 1) << 4)) ^ ((brow & 7) << 4)));

    auto issue = [&](int k, int part) {
        int slot = k % S;
        uint32_t base = tiles + slot * STG;
        const __half *Ap, *Bp; int ldA, ldB, kk;
        if (k < n1) { Ap = A1; Bp = B1; ldA = lda1; ldB = ldb1; kk = k * 64; }
        else        { Ap = A2; Bp = B2; ldA = NR;   ldB = NR;   kk = (k - n1) * 64; }
        if (part == 0) {
            #pragma unroll
            for (int i = 0; i < 4; i++) {
                int idx = tid + i * 256, row = idx >> 3, c16 = idx & 7;
                cp16(base + row * 128 + ((c16 * 16) ^ ((row & 7) << 4)),
                     Ap + (mBase + row) * (size_t)ldA + kk + c16 * 8);
            }
        } else {
            #pragma unroll
            for (int i = 0; i < 4; i++) {
                int idx = tid + (part - 1) * 1024 + i * 256;
                int row = idx >> 3, c16 = idx & 7;
                cp16(base + AST + row * 128 + ((c16 * 16) ^ ((row & 7) << 4)),
                     Bp + (nBase + row) * (size_t)ldB + kk + c16 * 8);
            }
        }
    };

    float acc[MI][NI][4];
    #pragma unroll
    for (int i = 0; i < MI; i++)
        #pragma unroll
        for (int j = 0; j < NI; j++)
            #pragma unroll
            for (int k = 0; k < 4; k++) acc[i][j][k] = 0.f;

    unsigned afX[MI][4], bgX[NI / 2][4];      // pingpong fragment buffers
    unsigned afY[MI][4], bgY[NI / 2][4];

    auto loadfrags = [&](uint32_t sbase, int ks,
                         unsigned af[MI][4], unsigned bg[NI / 2][4]) {
        const uint32_t kx = (uint32_t)(ks << 5);
        #pragma unroll
        for (int mi = 0; mi < MI; mi++)
            ldsm_x4(af[mi][0], af[mi][1], af[mi][2], af[mi][3],
                    (sbase + aoff0 + mi * 2048) ^ kx);
        #pragma unroll
        for (int g = 0; g < NI / 2; g++)
            ldsm_x4(bg[g][0], bg[g][1], bg[g][2], bg[g][3],
                    (sbase + boff0 + g * 2048) ^ kx);
    };

    // compute one k-step from (af,bg) while prefetching step `ks` of `sbase`
    // into (afn,bgn): 2 LDSM.x4 interleaved per 8 HMMAs.
    auto domma_pf = [&](unsigned af[MI][4], unsigned bg[NI / 2][4],
                        unsigned afn[MI][4], unsigned bgn[NI / 2][4],
                        uint32_t sbase, int ks) {
        const uint32_t kx = (uint32_t)(ks << 5);
        #pragma unroll
        for (int mi = 0; mi < MI; mi++) {
            ldsm_x4(afn[mi][0], afn[mi][1], afn[mi][2], afn[mi][3],
                    (sbase + aoff0 + mi * 2048) ^ kx);
            ldsm_x4(bgn[mi][0], bgn[mi][1], bgn[mi][2], bgn[mi][3],
                    (sbase + boff0 + mi * 2048) ^ kx);
            #pragma unroll
            for (int ni = 0; ni < NI; ni++) {
                unsigned b0 = bg[ni >> 1][(ni & 1) * 2];
                unsigned b1 = bg[ni >> 1][(ni & 1) * 2 + 1];
                asm volatile(
                    "mma.sync.aligned.m16n8k16.row.col.f32.f16.f16.f32 "
                    "{%0,%1,%2,%3}, {%4,%5,%6,%7}, {%8,%9}, {%0,%1,%2,%3};"
                    : "+f"(acc[mi][ni][0]), "+f"(acc[mi][ni][1]),
                      "+f"(acc[mi][ni][2]), "+f"(acc[mi][ni][3])
                    : "r"(af[mi][0]), "r"(af[mi][1]),
                      "r"(af[mi][2]), "r"(af[mi][3]),
                      "r"(b0), "r"(b1));
            }
        }
    };

    // prologue
    #pragma unroll
    for (int k = 0; k < S - 1; k++) {
        if (k < nIter) { issue(k, 0); issue(k, 1); issue(k, 2); }
        cp_commit();
    }
    cp_wait<S - 2>();
    __syncthreads();
    loadfrags(tiles, 0, afX, bgX);

    for (int k = 0; k < nIter; k++) {
        const uint32_t sbase = tiles + (k % S) * STG;
        const uint32_t snext = tiles + ((k + 1) % S) * STG;
        const bool more = (k + S - 1 < nIter);

        if (more) issue(k + S - 1, 0);
        domma_pf(afX, bgX, afY, bgY, sbase, 1);   // compute ks0, load ks1

        if (more) issue(k + S - 1, 1);
        domma_pf(afY, bgY, afX, bgX, sbase, 2);   // compute ks1, load ks2

        if (more) issue(k + S - 1, 2);
        domma_pf(afX, bgX, afY, bgY, sbase, 3);   // compute ks2, load ks3

        cp_commit();
        cp_wait<S - 2>();                         // stage k+1 resident
        __syncthreads();                          // all stage-k reads done
        domma_pf(afY, bgY, afX, bgX, snext, 0);   // compute ks3, load next ks0
    }

    // ---- epilogue: +bias, float2 stores ----
    #pragma unroll
    for (int mi = 0; mi < MI; mi++) {
        size_t row = mBase + warpRow + mi * 16 + gid;
        #pragma unroll
        for (int ni = 0; ni < NI; ni++) {
            size_t col = nBase + warpCol + ni * 8 + tig * 2;
            float b0 = __ldg(bias + col);
            float b1 = __ldg(bias + col + 1);
            float2 v0, v1;
            v0.x = acc[mi][ni][0] + b0; v0.y = acc[mi][ni][1] + b1;
            v1.x = acc[mi][ni][2] + b0; v1.y = acc[mi][ni][3] + b1;
            *reinterpret_cast<float2*>(C + row * (size_t)ldc + col)       = v0;
            *reinterpret_cast<float2*>(C + (row + 8) * (size_t)ldc + col) = v1;
        }
    }
}

extern "C" void kernel_launch(void* const* d_in, const int* in_sizes, int n_in,
                              void* d_out, int out_size) {
    const float* x      = (const float*)d_in[0];
    const float* lora_A = (const float*)d_in[1];
    const float* lora_B = (const float*)d_in[2];
    const float* W      = (const float*)d_in[3];
    const float* bias   = (const float*)d_in[4];
    const float* lw     = (const float*)d_in[5];
    float* out = (float*)d_out;

    __half *xh, *Wh, *Ah, *hh, *bch;
    cudaGetSymbolAddress((void**)&xh,  g_xh);
    cudaGetSymbolAddress((void**)&Wh,  g_Wh);
    cudaGetSymbolAddress((void**)&Ah,  g_Ah);
    cudaGetSymbolAddress((void**)&hh,  g_hh);
    cudaGetSymbolAddress((void**)&bch, g_Bch);

    // 0) convert x + lora_A; build Bc
    f2h_xa_kernel<<<2048, 256>>>((const float4*)x, (uint2*)xh,
                                 (const float4*)lora_A, (uint2*)Ah);
    build_bc_kernel<<<(DOUT * NR + 255) / 256, 256>>>(lora_B, lw);

    constexpr int SMEM1   = 3 * (64 + 128) * 40 * 2;    // 46,080 B
    constexpr int SMEMBIG = 4 * (128 + 256) * 128;      // 196,608 B
    cudaFuncSetAttribute(gemm1_f16,
                         cudaFuncAttributeMaxDynamicSharedMemorySize, SMEM1);
    cudaFuncSetAttribute(gemm_f16_big,
                         cudaFuncAttributeMaxDynamicSharedMemorySize, SMEMBIG);

    // 1) h = x @ A^T (128 CTAs)  ∥  W fp32->fp16 (64 CTAs)
    gemm1_f16<<<dim3(1, G1_MBLK + G1_WBLK), 256, SMEM1>>>(
        xh, DIN, Ah, DIN, DIN, hh, NR, W, Wh);

    // 2) out = x @ W^T + h @ Bc^T + bias
    gemm_f16_big<<<dim3(DOUT / 256, MTOT / 128), 256, SMEMBIG>>>(
        xh, DIN, Wh, DIN, DIN,
        hh, bch, NR,
        bias, out, DOUT);
}